// round 16
// baseline (speedup 1.0000x reference)
#include <cuda_runtime.h>
#include <cuda_fp16.h>
#include <math.h>
#include <stdint.h>

// Problem constants
#define NROWS 8192
#define DDIM  128
#define WVDIM 300
#define BIGF  1e8f
#define DEPS  1.28e-14f   // D * 1e-16
#define NEGINF -3.4e38f
#define POSINF  3.4e38f

// ---------------------------------------------------------------------------
// Scratch (__device__ globals; no allocation allowed)
// ---------------------------------------------------------------------------
__device__ float g_ssq[NROWS];
__device__ float g_xsq[NROWS];
// A side: fp16 of (-2*sem), row-major, 256 B/row (16 chunks of 16B)
__device__ __half g_semA[NROWS * 128];
// B side: fp16 of x, row-major, 256 B/row
__device__ __half g_xH[NROWS * 128];

// ---------------------------------------------------------------------------
// PTX helpers
// ---------------------------------------------------------------------------
__device__ __forceinline__ uint32_t smem_u32(const void* p) {
    uint32_t a;
    asm("{ .reg .u64 t; cvta.to.shared.u64 t, %1; cvt.u32.u64 %0, t; }" : "=r"(a) : "l"(p));
    return a;
}
__device__ __forceinline__ void ldsm_x4(uint32_t* r, uint32_t addr) {
    asm("ldmatrix.sync.aligned.m8n8.x4.shared.b16 {%0,%1,%2,%3}, [%4];"
        : "=r"(r[0]), "=r"(r[1]), "=r"(r[2]), "=r"(r[3]) : "r"(addr) : "memory");
}
__device__ __forceinline__ void mma16816h(float* d, const uint32_t* a, const uint32_t* b) {
    asm("mma.sync.aligned.m16n8k16.row.col.f32.f16.f16.f32 "
        "{%0,%1,%2,%3}, {%4,%5,%6,%7}, {%8,%9}, {%0,%1,%2,%3};"
        : "+f"(d[0]), "+f"(d[1]), "+f"(d[2]), "+f"(d[3])
        : "r"(a[0]), "r"(a[1]), "r"(a[2]), "r"(a[3]), "r"(b[0]), "r"(b[1]));
}
__device__ __forceinline__ void cp16(uint32_t dst, const void* src) {
    asm volatile("cp.async.cg.shared.global [%0], [%1], 16;" :: "r"(dst), "l"(src) : "memory");
}
__device__ __forceinline__ void cp_commit() {
    asm volatile("cp.async.commit_group;" ::: "memory");
}
__device__ __forceinline__ void cp_wait0() {
    asm volatile("cp.async.wait_group 0;" ::: "memory");
}
__device__ __forceinline__ void cp_wait1() {
    asm volatile("cp.async.wait_group 1;" ::: "memory");
}
__device__ __forceinline__ void bar_named(int id, int nthreads) {
    asm volatile("bar.sync %0, %1;" :: "r"(id), "r"(nthreads) : "memory");
}

// ---------------------------------------------------------------------------
// Kernel A (fused): sem = alpha*(wv@W^T + b) + (1-alpha)*x,  PLUS:
//   sem -> output, fp16 of (-2*sem) -> g_semA, fp16 of x -> g_xH, row norms.
// (UNCHANGED from R14/R15 — 18.7 us measured.)
// ---------------------------------------------------------------------------
#define FC_ROWS    64
#define FC_KC      100
#define FC_CHUNKS  3
#define W_FLOATS   (DDIM * FC_KC)      // 12800
#define WVV_FLOATS (FC_ROWS * FC_KC)   // 6400
#define FC_SMEM    (2 * (W_FLOATS + WVV_FLOATS) * 4)   // 153600 B

__global__ __launch_bounds__(256) void fc_mix_fused(
    const float* __restrict__ wv, const float* __restrict__ W,
    const float* __restrict__ b, const float* __restrict__ alpha,
    const float* __restrict__ x, float* __restrict__ sem_out)
{
    extern __shared__ float fsm[];
    float* Wt  = fsm;                     // [2][128][100]  row-major
    float* wvt = fsm + 2 * W_FLOATS;      // [2][64][100]   row-major

    const int tid  = threadIdx.x;
    const int tx   = tid & 15;            // d-lane 0..15
    const int ty   = tid >> 4;            // m-group 0..15
    const int row0 = blockIdx.x * FC_ROWS;

    const uint32_t WtU  = smem_u32(Wt);
    const uint32_t wvtU = smem_u32(wvt);

    auto stage_chunk = [&](int c, int buf) {
        uint32_t wdst = WtU + (uint32_t)(buf * W_FLOATS * 4);
        const float* wsrc = W + c * FC_KC;
        #pragma unroll 4
        for (int l = tid; l < DDIM * (FC_KC / 4); l += 256) {   // 3200 f4
            int d = l / 25, f4 = l - d * 25;
            cp16(wdst + (uint32_t)l * 16, wsrc + (size_t)d * WVDIM + f4 * 4);
        }
        uint32_t vdst = wvtU + (uint32_t)(buf * WVV_FLOATS * 4);
        const float* vsrc = wv + (size_t)row0 * WVDIM + c * FC_KC;
        #pragma unroll 4
        for (int l = tid; l < FC_ROWS * (FC_KC / 4); l += 256) { // 1600 f4
            int m = l / 25, f4 = l - m * 25;
            cp16(vdst + (uint32_t)l * 16, vsrc + (size_t)m * WVDIM + f4 * 4);
        }
    };

    float acc[4][8];
    #pragma unroll
    for (int i = 0; i < 4; i++)
        #pragma unroll
        for (int j = 0; j < 8; j++) acc[i][j] = 0.f;

    stage_chunk(0, 0);
    cp_commit();

    for (int c = 0; c < FC_CHUNKS; c++) {
        const int buf = c & 1;
        cp_wait0();
        __syncthreads();
        if (c + 1 < FC_CHUNKS) {
            stage_chunk(c + 1, buf ^ 1);
            cp_commit();
        }
        const float4* Wd  = reinterpret_cast<const float4*>(Wt  + buf * W_FLOATS);
        const float4* wvd = reinterpret_cast<const float4*>(wvt + buf * WVV_FLOATS);

        #pragma unroll 5
        for (int k4 = 0; k4 < FC_KC / 4; k4++) {
            float4 wf[8], vf[4];
            #pragma unroll
            for (int j = 0; j < 8; j++) wf[j] = Wd[(tx + 16 * j) * 25 + k4];
            #pragma unroll
            for (int i = 0; i < 4; i++) vf[i] = wvd[(ty * 4 + i) * 25 + k4];
            #pragma unroll
            for (int i = 0; i < 4; i++) {
                #pragma unroll
                for (int j = 0; j < 8; j++) {
                    float s = acc[i][j];
                    s = fmaf(vf[i].x, wf[j].x, s);
                    s = fmaf(vf[i].y, wf[j].y, s);
                    s = fmaf(vf[i].z, wf[j].z, s);
                    s = fmaf(vf[i].w, wf[j].w, s);
                    acc[i][j] = s;
                }
            }
        }
    }

    float bd[8];
    #pragma unroll
    for (int j = 0; j < 8; j++) bd[j] = b[tx + 16 * j];

    #pragma unroll
    for (int i = 0; i < 4; i++) {
        const int row = row0 + ty * 4 + i;
        const float al = alpha[row];
        float xv[8];
        #pragma unroll
        for (int j = 0; j < 8; j++) xv[j] = x[(size_t)row * DDIM + tx + 16 * j];

        float sv[8];
        float pssq = 0.f, pxsq = 0.f;
        #pragma unroll
        for (int j = 0; j < 8; j++) {
            float s = al * (acc[i][j] + bd[j]) + (1.f - al) * xv[j];
            sv[j] = s;
            pssq = fmaf(s, s, pssq);
            pxsq = fmaf(xv[j], xv[j], pxsq);
        }

        #pragma unroll
        for (int j = 0; j < 8; j++) {
            sem_out[(size_t)row * DDIM + tx + 16 * j] = sv[j];
            g_semA[(size_t)row * DDIM + tx + 16 * j] = __float2half(-2.f * sv[j]);
            g_xH[(size_t)row * DDIM + tx + 16 * j]   = __float2half(xv[j]);
        }

        #pragma unroll
        for (int o = 1; o <= 8; o <<= 1) {
            pssq += __shfl_xor_sync(0xFFFFFFFFu, pssq, o);
            pxsq += __shfl_xor_sync(0xFFFFFFFFu, pxsq, o);
        }
        if (tx == 0) {
            g_ssq[row] = pssq;
            g_xsq[row] = pxsq;
        }
    }
}

// ---------------------------------------------------------------------------
// Kernel B: persistent distance + batch-hard mining, 512 threads (16 warps),
// pair-decoupled (8 pairs of 16-col slabs).  NEW vs R15:
//   - TRIPLE-buffered slabs -> ONE named barrier per tile (stage t+2 after
//     barrier t writes buf (t-1)%3, which all pair warps finished before
//     arriving at barrier t).
//   - xsq + labels staged into the slab via the same cp.async group ->
//     mining metadata is LDS broadcast, not per-tile LDG.
// ---------------------------------------------------------------------------
#define A_BYTES     16384                   // 64 rows x 256 B
#define SLAB_DATA   4096                    // 16 rows x 256 B
#define SLAB_STRIDE 4352                    // + 64 B xsq + 64 B labels (256-aligned)
#define PAIR_BYTES  (3 * SLAB_STRIDE)       // 13056
#define DIST_DSMEM  (A_BYTES + 8 * PAIR_BYTES)   // 120832

#define NSTEPS 64

__global__ __launch_bounds__(512, 1) void dist_persist(
    const int* __restrict__ label, float* __restrict__ diff_out)
{
    extern __shared__ char dyn[];
    __shared__ float aggF[8 * 64];
    __shared__ float aggC[8 * 64];

    const int tid  = threadIdx.x;
    const int wid  = tid >> 5;
    const int lane = tid & 31;
    const int rowbase = blockIdx.x * 64;

    // ---- stage A strip (64 rows x 16 chunks of 16B), swizzled key r&7 ----
    {
        const uint4* gA = reinterpret_cast<const uint4*>(g_semA) + (size_t)rowbase * 16;
        #pragma unroll
        for (int it = 0; it < 2; it++) {
            int idx = it * 512 + tid;          // 0..1023
            int r = idx >> 4, cch = idx & 15;
            uint32_t off = (uint32_t)(r * 256 + ((cch ^ (r & 7)) << 4));
            *reinterpret_cast<uint4*>(dyn + off) = gA[(size_t)r * 16 + cch];
        }
    }
    __syncthreads();

    const uint32_t AsU = smem_u32(dyn);

    const int wm = wid & 1;            // 2 m-slabs of 32
    const int wn = wid >> 1;           // 8 n-slabs of 16 (= pair id)
    const int m_base = wm * 32;
    const int n_base = wn * 16;
    const int pt     = wm * 32 + lane; // pair-local thread 0..63
    const int barid  = 1 + wn;         // named barriers 1..8

    char*          pairPtr = dyn + A_BYTES + wn * PAIR_BYTES;
    const uint32_t pairU   = AsU + A_BYTES + wn * PAIR_BYTES;

    // ---- preload ALL A fragments (hi only) into registers ----
    uint32_t aF[8][2][4];              // [kstep][mt][4]
    {
        const uint32_t a_chunk_add = (uint32_t)(lane >> 4);
        #pragma unroll
        for (int mt = 0; mt < 2; mt++) {
            int r = m_base + mt * 16 + (lane & 15);
            uint32_t base = AsU + r * 256;
            uint32_t sw   = (uint32_t)(r & 7);
            #pragma unroll
            for (int s = 0; s < 8; s++) {
                uint32_t ch = (uint32_t)(s * 2) + a_chunk_add;
                ldsm_x4(aF[s][mt], base + ((ch ^ sw) << 4));
            }
        }
    }

    // B ldsm addressing within a 16-row x 256B slab
    const int brow = ((lane >> 4) << 3) + (lane & 7);    // 0..15
    const uint32_t b_off = pairU + brow * 256;
    const uint32_t b_sw  = (uint32_t)(brow & 7);
    const uint32_t b_chunk_add = (uint32_t)((lane >> 3) & 1);

    // per-thread row info
    const int q  = lane >> 2;
    const int qt = lane & 3;
    int row_gi[2][2];
    int lmv[2][2];
    #pragma unroll
    for (int mt = 0; mt < 2; mt++)
        #pragma unroll
        for (int hr = 0; hr < 2; hr++) {
            row_gi[mt][hr] = rowbase + m_base + mt * 16 + hr * 8 + q;
            lmv[mt][hr]    = label[row_gi[mt][hr]];
        }

    float fpU[2][2], cnU[2][2];
    #pragma unroll
    for (int mt = 0; mt < 2; mt++)
        #pragma unroll
        for (int hr = 0; hr < 2; hr++) { fpU[mt][hr] = NEGINF; cnU[mt][hr] = POSINF; }

    // ---- slab staging: 16 rows x 16 chunks + metadata, 64 threads ----
    auto stage_slab = [&](int t, int buf) {
        const char* gB = reinterpret_cast<const char*>(g_xH)
                       + (size_t)(t * 128 + n_base) * 256;
        uint32_t bb = pairU + buf * SLAB_STRIDE;
        #pragma unroll
        for (int it = 0; it < 4; it++) {
            int idx = it * 64 + pt;            // 0..255
            int r = idx >> 4, cch = idx & 15;
            uint32_t dst = bb + (uint32_t)(r * 256 + ((cch ^ (r & 7)) << 4));
            cp16(dst, gB + (size_t)r * 256 + cch * 16);
        }
        // metadata: 16 floats xsq @ +4096, 16 ints labels @ +4160
        if (pt < 4) {
            cp16(bb + 4096u + pt * 16, g_xsq + (t * 128 + n_base) + pt * 4);
        } else if (pt < 8) {
            cp16(bb + 4160u + (pt - 4) * 16, label + (t * 128 + n_base) + (pt - 4) * 4);
        }
    };

    const int t_diag = (int)(blockIdx.x >> 1);

    stage_slab(0, 0); cp_commit();
    stage_slab(1, 1); cp_commit();

    int buf = 0;
    for (int t = 0; t < NSTEPS; t++) {
        const int n0 = t * 128;

        if (t + 1 < NSTEPS) cp_wait1();    // tile t staged (t+1 still in flight)
        else                cp_wait0();
        bar_named(barid, 64);              // single barrier: tile t visible AND
                                           // all pair warps done with tile t-1
        if (t + 2 < NSTEPS) {
            int nb = buf + 2; if (nb >= 3) nb -= 3;
            stage_slab(t + 2, nb);         // writes buf (t-1)%3: safe post-barrier
            cp_commit();
        }

        // mining metadata from slab (LDS broadcast)
        const float* xqS = reinterpret_cast<const float*>(pairPtr + buf * SLAB_STRIDE + 4096);
        const int*   lbS = reinterpret_cast<const int*>  (pairPtr + buf * SLAB_STRIDE + 4160);
        float xq[4]; int lb[4];
        #pragma unroll
        for (int k = 0; k < 4; k++) {
            int cl = (k >> 1) * 8 + qt * 2 + (k & 1);   // local col 0..15
            xq[k] = xqS[cl];
            lb[k] = lbS[cl];
        }

        float c[2][2][4];
        #pragma unroll
        for (int mt = 0; mt < 2; mt++)
            #pragma unroll
            for (int nt = 0; nt < 2; nt++)
                #pragma unroll
                for (int e = 0; e < 4; e++) c[mt][nt][e] = 0.f;

        const uint32_t bufAdd = (uint32_t)(buf * SLAB_STRIDE);
        #pragma unroll
        for (int s = 0; s < 8; s++) {
            uint32_t bfr[4];
            uint32_t chB = (uint32_t)(s * 2) + b_chunk_add;
            ldsm_x4(bfr, b_off + bufAdd + ((chB ^ b_sw) << 4));

            #pragma unroll
            for (int mt = 0; mt < 2; mt++) {
                #pragma unroll
                for (int nt = 0; nt < 2; nt++) {
                    mma16816h(c[mt][nt], aF[s][mt], &bfr[nt * 2]);   // Ah*Bh
                }
            }
        }

        // ---- mining on u = xsq[col] + (-2 sem.x) ----
        if (t == t_diag) {
            #pragma unroll
            for (int mt = 0; mt < 2; mt++) {
                #pragma unroll
                for (int hr = 0; hr < 2; hr++) {
                    const int gi = row_gi[mt][hr];
                    const int lm = lmv[mt][hr];
                    float fb = fpU[mt][hr], cb = cnU[mt][hr];
                    #pragma unroll
                    for (int nt = 0; nt < 2; nt++) {
                        #pragma unroll
                        for (int w = 0; w < 2; w++) {
                            int k  = nt * 2 + w;
                            int cl = n0 + n_base + nt * 8 + qt * 2 + w;
                            float u = xq[k] + c[mt][nt][hr * 2 + w];
                            bool same = (lm == lb[k]);
                            bool self = (cl == gi);
                            fb = fmaxf(fb, (same && !self) ? u : NEGINF);
                            cb = fminf(cb, same ? POSINF : u);
                        }
                    }
                    fpU[mt][hr] = fb;
                    cnU[mt][hr] = cb;
                }
            }
        } else {
            #pragma unroll
            for (int mt = 0; mt < 2; mt++) {
                #pragma unroll
                for (int hr = 0; hr < 2; hr++) {
                    const int lm = lmv[mt][hr];
                    float fb = fpU[mt][hr], cb = cnU[mt][hr];
                    #pragma unroll
                    for (int nt = 0; nt < 2; nt++) {
                        #pragma unroll
                        for (int w = 0; w < 2; w++) {
                            int k = nt * 2 + w;
                            float u = xq[k] + c[mt][nt][hr * 2 + w];
                            bool same = (lm == lb[k]);
                            fb = fmaxf(fb, same ? u : NEGINF);
                            cb = fminf(cb, same ? POSINF : u);
                        }
                    }
                    fpU[mt][hr] = fb;
                    cnU[mt][hr] = cb;
                }
            }
        }

        if (++buf >= 3) buf = 0;
    }

    // ---- final reduction: quad lanes -> smem across wn warps -> softplus ----
    #pragma unroll
    for (int mt = 0; mt < 2; mt++) {
        #pragma unroll
        for (int hr = 0; hr < 2; hr++) {
            float fb = fpU[mt][hr], cb = cnU[mt][hr];
            #pragma unroll
            for (int o = 1; o <= 2; o <<= 1) {
                fb = fmaxf(fb, __shfl_xor_sync(0xFFFFFFFFu, fb, o));
                cb = fminf(cb, __shfl_xor_sync(0xFFFFFFFFu, cb, o));
            }
            if (qt == 0) {
                int r = m_base + mt * 16 + hr * 8 + q;
                aggF[wn * 64 + r] = fb;
                aggC[wn * 64 + r] = cb;
            }
        }
    }
    __syncthreads();

    if (tid < 64) {
        float fb = NEGINF, cb = POSINF;
        #pragma unroll
        for (int wnn = 0; wnn < 8; wnn++) {
            fb = fmaxf(fb, aggF[wnn * 64 + tid]);
            cb = fminf(cb, aggC[wnn * 64 + tid]);
        }
        float ssqm = g_ssq[rowbase + tid];
        float fp = (fb < -1e37f) ? 0.f : sqrtf(fmaxf(ssqm + fb, 0.f) + DEPS);
        float cn = sqrtf(fmaxf(ssqm + cb, 0.f) + DEPS);
        float z = fp - cn;
        diff_out[rowbase + tid] = fmaxf(z, 0.f) + log1pf(expf(-fabsf(z)));
    }
}

// ---------------------------------------------------------------------------
// Launch
// Inputs: x[N,128] f32, wv[N,300] f32, label[N] i32, alpha[N,1] f32,
//         W[128,300] f32, b[128] f32
// Output: diff[N] then sem[N,128] (float32, concatenated)
// ---------------------------------------------------------------------------
extern "C" void kernel_launch(void* const* d_in, const int* in_sizes, int n_in,
                              void* d_out, int out_size)
{
    const float* x     = (const float*)d_in[0];
    const float* wv    = (const float*)d_in[1];
    const int*   label = (const int*)  d_in[2];
    const float* alpha = (const float*)d_in[3];
    const float* W     = (const float*)d_in[4];
    const float* b     = (const float*)d_in[5];

    float* out  = (float*)d_out;
    float* diff = out;            // [N]
    float* sem  = out + NROWS;    // [N, 128]

    static bool attr_set = false;
    if (!attr_set) {
        cudaFuncSetAttribute(dist_persist,
                             cudaFuncAttributeMaxDynamicSharedMemorySize, DIST_DSMEM);
        cudaFuncSetAttribute(fc_mix_fused,
                             cudaFuncAttributeMaxDynamicSharedMemorySize, FC_SMEM);
        attr_set = true;
    }

    fc_mix_fused<<<NROWS / FC_ROWS, 256, FC_SMEM>>>(wv, W, b, alpha, x, sem);
    dist_persist<<<NROWS / 64, 512, DIST_DSMEM>>>(label, diff);
}

// round 17
// speedup vs baseline: 1.0454x; 1.0454x over previous
#include <cuda_runtime.h>
#include <cuda_fp16.h>
#include <math.h>
#include <stdint.h>

// Problem constants
#define NROWS 8192
#define DDIM  128
#define WVDIM 300
#define BIGF  1e8f
#define DEPS  1.28e-14f   // D * 1e-16
#define NEGINF -3.4e38f
#define POSINF  3.4e38f

// ---------------------------------------------------------------------------
// Scratch (__device__ globals; no allocation allowed)
// ---------------------------------------------------------------------------
__device__ float g_ssq[NROWS];
__device__ float g_xsq[NROWS];
// A side: fp16 of (-2*sem), row-major, 256 B/row (16 chunks of 16B)
__device__ __half g_semA[NROWS * 128];
// B side: fp16 of x, row-major, 256 B/row
__device__ __half g_xH[NROWS * 128];

// ---------------------------------------------------------------------------
// PTX helpers
// ---------------------------------------------------------------------------
__device__ __forceinline__ uint32_t smem_u32(const void* p) {
    uint32_t a;
    asm("{ .reg .u64 t; cvta.to.shared.u64 t, %1; cvt.u32.u64 %0, t; }" : "=r"(a) : "l"(p));
    return a;
}
__device__ __forceinline__ void ldsm_x4(uint32_t* r, uint32_t addr) {
    asm("ldmatrix.sync.aligned.m8n8.x4.shared.b16 {%0,%1,%2,%3}, [%4];"
        : "=r"(r[0]), "=r"(r[1]), "=r"(r[2]), "=r"(r[3]) : "r"(addr) : "memory");
}
__device__ __forceinline__ void mma16816h(float* d, const uint32_t* a, const uint32_t* b) {
    asm("mma.sync.aligned.m16n8k16.row.col.f32.f16.f16.f32 "
        "{%0,%1,%2,%3}, {%4,%5,%6,%7}, {%8,%9}, {%0,%1,%2,%3};"
        : "+f"(d[0]), "+f"(d[1]), "+f"(d[2]), "+f"(d[3])
        : "r"(a[0]), "r"(a[1]), "r"(a[2]), "r"(a[3]), "r"(b[0]), "r"(b[1]));
}
__device__ __forceinline__ void cp16(uint32_t dst, const void* src) {
    asm volatile("cp.async.cg.shared.global [%0], [%1], 16;" :: "r"(dst), "l"(src) : "memory");
}
__device__ __forceinline__ void cp_commit() {
    asm volatile("cp.async.commit_group;" ::: "memory");
}
__device__ __forceinline__ void cp_wait0() {
    asm volatile("cp.async.wait_group 0;" ::: "memory");
}
__device__ __forceinline__ void cp_wait1() {
    asm volatile("cp.async.wait_group 1;" ::: "memory");
}
__device__ __forceinline__ void bar_named(int id, int nthreads) {
    asm volatile("bar.sync %0, %1;" :: "r"(id), "r"(nthreads) : "memory");
}

// ---------------------------------------------------------------------------
// Kernel A (fused): sem = alpha*(wv@W^T + b) + (1-alpha)*x,  PLUS:
//   sem -> output, fp16 of (-2*sem) -> g_semA, fp16 of x -> g_xH, row norms.
// (UNCHANGED from R14/R15 — 18.7 us measured.)
// ---------------------------------------------------------------------------
#define FC_ROWS    64
#define FC_KC      100
#define FC_CHUNKS  3
#define W_FLOATS   (DDIM * FC_KC)      // 12800
#define WVV_FLOATS (FC_ROWS * FC_KC)   // 6400
#define FC_SMEM    (2 * (W_FLOATS + WVV_FLOATS) * 4)   // 153600 B

__global__ __launch_bounds__(256) void fc_mix_fused(
    const float* __restrict__ wv, const float* __restrict__ W,
    const float* __restrict__ b, const float* __restrict__ alpha,
    const float* __restrict__ x, float* __restrict__ sem_out)
{
    extern __shared__ float fsm[];
    float* Wt  = fsm;                     // [2][128][100]  row-major
    float* wvt = fsm + 2 * W_FLOATS;      // [2][64][100]   row-major

    const int tid  = threadIdx.x;
    const int tx   = tid & 15;            // d-lane 0..15
    const int ty   = tid >> 4;            // m-group 0..15
    const int row0 = blockIdx.x * FC_ROWS;

    const uint32_t WtU  = smem_u32(Wt);
    const uint32_t wvtU = smem_u32(wvt);

    auto stage_chunk = [&](int c, int buf) {
        uint32_t wdst = WtU + (uint32_t)(buf * W_FLOATS * 4);
        const float* wsrc = W + c * FC_KC;
        #pragma unroll 4
        for (int l = tid; l < DDIM * (FC_KC / 4); l += 256) {   // 3200 f4
            int d = l / 25, f4 = l - d * 25;
            cp16(wdst + (uint32_t)l * 16, wsrc + (size_t)d * WVDIM + f4 * 4);
        }
        uint32_t vdst = wvtU + (uint32_t)(buf * WVV_FLOATS * 4);
        const float* vsrc = wv + (size_t)row0 * WVDIM + c * FC_KC;
        #pragma unroll 4
        for (int l = tid; l < FC_ROWS * (FC_KC / 4); l += 256) { // 1600 f4
            int m = l / 25, f4 = l - m * 25;
            cp16(vdst + (uint32_t)l * 16, vsrc + (size_t)m * WVDIM + f4 * 4);
        }
    };

    float acc[4][8];
    #pragma unroll
    for (int i = 0; i < 4; i++)
        #pragma unroll
        for (int j = 0; j < 8; j++) acc[i][j] = 0.f;

    stage_chunk(0, 0);
    cp_commit();

    for (int c = 0; c < FC_CHUNKS; c++) {
        const int buf = c & 1;
        cp_wait0();
        __syncthreads();
        if (c + 1 < FC_CHUNKS) {
            stage_chunk(c + 1, buf ^ 1);
            cp_commit();
        }
        const float4* Wd  = reinterpret_cast<const float4*>(Wt  + buf * W_FLOATS);
        const float4* wvd = reinterpret_cast<const float4*>(wvt + buf * WVV_FLOATS);

        #pragma unroll 5
        for (int k4 = 0; k4 < FC_KC / 4; k4++) {
            float4 wf[8], vf[4];
            #pragma unroll
            for (int j = 0; j < 8; j++) wf[j] = Wd[(tx + 16 * j) * 25 + k4];
            #pragma unroll
            for (int i = 0; i < 4; i++) vf[i] = wvd[(ty * 4 + i) * 25 + k4];
            #pragma unroll
            for (int i = 0; i < 4; i++) {
                #pragma unroll
                for (int j = 0; j < 8; j++) {
                    float s = acc[i][j];
                    s = fmaf(vf[i].x, wf[j].x, s);
                    s = fmaf(vf[i].y, wf[j].y, s);
                    s = fmaf(vf[i].z, wf[j].z, s);
                    s = fmaf(vf[i].w, wf[j].w, s);
                    acc[i][j] = s;
                }
            }
        }
    }

    float bd[8];
    #pragma unroll
    for (int j = 0; j < 8; j++) bd[j] = b[tx + 16 * j];

    #pragma unroll
    for (int i = 0; i < 4; i++) {
        const int row = row0 + ty * 4 + i;
        const float al = alpha[row];
        float xv[8];
        #pragma unroll
        for (int j = 0; j < 8; j++) xv[j] = x[(size_t)row * DDIM + tx + 16 * j];

        float sv[8];
        float pssq = 0.f, pxsq = 0.f;
        #pragma unroll
        for (int j = 0; j < 8; j++) {
            float s = al * (acc[i][j] + bd[j]) + (1.f - al) * xv[j];
            sv[j] = s;
            pssq = fmaf(s, s, pssq);
            pxsq = fmaf(xv[j], xv[j], pxsq);
        }

        #pragma unroll
        for (int j = 0; j < 8; j++) {
            sem_out[(size_t)row * DDIM + tx + 16 * j] = sv[j];
            g_semA[(size_t)row * DDIM + tx + 16 * j] = __float2half(-2.f * sv[j]);
            g_xH[(size_t)row * DDIM + tx + 16 * j]   = __float2half(xv[j]);
        }

        #pragma unroll
        for (int o = 1; o <= 8; o <<= 1) {
            pssq += __shfl_xor_sync(0xFFFFFFFFu, pssq, o);
            pxsq += __shfl_xor_sync(0xFFFFFFFFu, pxsq, o);
        }
        if (tx == 0) {
            g_ssq[row] = pssq;
            g_xsq[row] = pxsq;
        }
    }
}

// ---------------------------------------------------------------------------
// Kernel B: persistent distance + batch-hard mining, 512 threads (16 warps),
// pair-decoupled (8 pairs of 16-col slabs).  Structure = R15 (double buffer,
// 2 named barriers/tile — proven 71.3 us).  ONLY change vs R15: xsq + labels
// staged into the slab via the same cp.async group -> mining metadata is
// LDS broadcast, not 8 per-tile LDGs at a dependency point.
// ---------------------------------------------------------------------------
#define A_BYTES     16384                   // 64 rows x 256 B
#define SLAB_DATA   4096                    // 16 rows x 256 B
#define SLAB_STRIDE 4352                    // + 64 B xsq + 64 B labels
#define PAIR_BYTES  (2 * SLAB_STRIDE)       // 8704
#define DIST_DSMEM  (A_BYTES + 8 * PAIR_BYTES)   // 86016

#define NSTEPS 64

__global__ __launch_bounds__(512, 1) void dist_persist(
    const int* __restrict__ label, float* __restrict__ diff_out)
{
    extern __shared__ char dyn[];
    __shared__ float aggF[8 * 64];
    __shared__ float aggC[8 * 64];

    const int tid  = threadIdx.x;
    const int wid  = tid >> 5;
    const int lane = tid & 31;
    const int rowbase = blockIdx.x * 64;

    // ---- stage A strip (64 rows x 16 chunks of 16B), swizzled key r&7 ----
    {
        const uint4* gA = reinterpret_cast<const uint4*>(g_semA) + (size_t)rowbase * 16;
        #pragma unroll
        for (int it = 0; it < 2; it++) {
            int idx = it * 512 + tid;          // 0..1023
            int r = idx >> 4, cch = idx & 15;
            uint32_t off = (uint32_t)(r * 256 + ((cch ^ (r & 7)) << 4));
            *reinterpret_cast<uint4*>(dyn + off) = gA[(size_t)r * 16 + cch];
        }
    }
    __syncthreads();

    const uint32_t AsU = smem_u32(dyn);

    const int wm = wid & 1;            // 2 m-slabs of 32
    const int wn = wid >> 1;           // 8 n-slabs of 16 (= pair id)
    const int m_base = wm * 32;
    const int n_base = wn * 16;
    const int pt     = wm * 32 + lane; // pair-local thread 0..63
    const int barid  = 1 + wn;         // named barriers 1..8

    char*          pairPtr = dyn + A_BYTES + wn * PAIR_BYTES;
    const uint32_t pairU   = AsU + A_BYTES + wn * PAIR_BYTES;

    // ---- preload ALL A fragments (hi only) into registers ----
    uint32_t aF[8][2][4];              // [kstep][mt][4]
    {
        const uint32_t a_chunk_add = (uint32_t)(lane >> 4);
        #pragma unroll
        for (int mt = 0; mt < 2; mt++) {
            int r = m_base + mt * 16 + (lane & 15);
            uint32_t base = AsU + r * 256;
            uint32_t sw   = (uint32_t)(r & 7);
            #pragma unroll
            for (int s = 0; s < 8; s++) {
                uint32_t ch = (uint32_t)(s * 2) + a_chunk_add;
                ldsm_x4(aF[s][mt], base + ((ch ^ sw) << 4));
            }
        }
    }

    // B ldsm addressing within a 16-row x 256B slab
    const int brow = ((lane >> 4) << 3) + (lane & 7);    // 0..15
    const uint32_t b_off = pairU + brow * 256;
    const uint32_t b_sw  = (uint32_t)(brow & 7);
    const uint32_t b_chunk_add = (uint32_t)((lane >> 3) & 1);

    // per-thread row info
    const int q  = lane >> 2;
    const int qt = lane & 3;
    int row_gi[2][2];
    int lmv[2][2];
    #pragma unroll
    for (int mt = 0; mt < 2; mt++)
        #pragma unroll
        for (int hr = 0; hr < 2; hr++) {
            row_gi[mt][hr] = rowbase + m_base + mt * 16 + hr * 8 + q;
            lmv[mt][hr]    = label[row_gi[mt][hr]];
        }

    float fpU[2][2], cnU[2][2];
    #pragma unroll
    for (int mt = 0; mt < 2; mt++)
        #pragma unroll
        for (int hr = 0; hr < 2; hr++) { fpU[mt][hr] = NEGINF; cnU[mt][hr] = POSINF; }

    // ---- slab staging: 16 rows x 16 chunks + metadata, 64 threads ----
    auto stage_slab = [&](int t, int buf) {
        const char* gB = reinterpret_cast<const char*>(g_xH)
                       + (size_t)(t * 128 + n_base) * 256;
        uint32_t bb = pairU + (uint32_t)(buf * SLAB_STRIDE);
        #pragma unroll
        for (int it = 0; it < 4; it++) {
            int idx = it * 64 + pt;            // 0..255
            int r = idx >> 4, cch = idx & 15;
            uint32_t dst = bb + (uint32_t)(r * 256 + ((cch ^ (r & 7)) << 4));
            cp16(dst, gB + (size_t)r * 256 + cch * 16);
        }
        // metadata: 16 floats xsq @ +4096, 16 ints labels @ +4160
        if (pt < 4) {
            cp16(bb + 4096u + pt * 16, g_xsq + (t * 128 + n_base) + pt * 4);
        } else if (pt < 8) {
            cp16(bb + 4160u + (pt - 4) * 16, label + (t * 128 + n_base) + (pt - 4) * 4);
        }
    };

    const int t_diag = (int)(blockIdx.x >> 1);

    stage_slab(0, 0);
    cp_commit();

    for (int t = 0; t < NSTEPS; t++) {
        const int buf = t & 1;
        const int n0  = t * 128;

        if (t + 1 < NSTEPS) {
            stage_slab(t + 1, buf ^ 1);
            cp_commit();
            cp_wait1();
        } else {
            cp_wait0();
        }
        bar_named(barid, 64);

        // mining metadata from slab (LDS broadcast)
        const float* xqS = reinterpret_cast<const float*>(pairPtr + buf * SLAB_STRIDE + 4096);
        const int*   lbS = reinterpret_cast<const int*>  (pairPtr + buf * SLAB_STRIDE + 4160);
        float xq[4]; int lb[4];
        #pragma unroll
        for (int k = 0; k < 4; k++) {
            int cl = (k >> 1) * 8 + qt * 2 + (k & 1);   // local col 0..15
            xq[k] = xqS[cl];
            lb[k] = lbS[cl];
        }

        float c[2][2][4];
        #pragma unroll
        for (int mt = 0; mt < 2; mt++)
            #pragma unroll
            for (int nt = 0; nt < 2; nt++)
                #pragma unroll
                for (int e = 0; e < 4; e++) c[mt][nt][e] = 0.f;

        const uint32_t bufAdd = (uint32_t)(buf * SLAB_STRIDE);
        #pragma unroll
        for (int s = 0; s < 8; s++) {
            uint32_t bfr[4];
            uint32_t chB = (uint32_t)(s * 2) + b_chunk_add;
            ldsm_x4(bfr, b_off + bufAdd + ((chB ^ b_sw) << 4));

            #pragma unroll
            for (int mt = 0; mt < 2; mt++) {
                #pragma unroll
                for (int nt = 0; nt < 2; nt++) {
                    mma16816h(c[mt][nt], aF[s][mt], &bfr[nt * 2]);   // Ah*Bh
                }
            }
        }

        // ---- mining on u = xsq[col] + (-2 sem.x) ----
        if (t == t_diag) {
            #pragma unroll
            for (int mt = 0; mt < 2; mt++) {
                #pragma unroll
                for (int hr = 0; hr < 2; hr++) {
                    const int gi = row_gi[mt][hr];
                    const int lm = lmv[mt][hr];
                    float fb = fpU[mt][hr], cb = cnU[mt][hr];
                    #pragma unroll
                    for (int nt = 0; nt < 2; nt++) {
                        #pragma unroll
                        for (int w = 0; w < 2; w++) {
                            int k  = nt * 2 + w;
                            int cl = n0 + n_base + nt * 8 + qt * 2 + w;
                            float u = xq[k] + c[mt][nt][hr * 2 + w];
                            bool same = (lm == lb[k]);
                            bool self = (cl == gi);
                            fb = fmaxf(fb, (same && !self) ? u : NEGINF);
                            cb = fminf(cb, same ? POSINF : u);
                        }
                    }
                    fpU[mt][hr] = fb;
                    cnU[mt][hr] = cb;
                }
            }
        } else {
            #pragma unroll
            for (int mt = 0; mt < 2; mt++) {
                #pragma unroll
                for (int hr = 0; hr < 2; hr++) {
                    const int lm = lmv[mt][hr];
                    float fb = fpU[mt][hr], cb = cnU[mt][hr];
                    #pragma unroll
                    for (int nt = 0; nt < 2; nt++) {
                        #pragma unroll
                        for (int w = 0; w < 2; w++) {
                            int k = nt * 2 + w;
                            float u = xq[k] + c[mt][nt][hr * 2 + w];
                            bool same = (lm == lb[k]);
                            fb = fmaxf(fb, same ? u : NEGINF);
                            cb = fminf(cb, same ? POSINF : u);
                        }
                    }
                    fpU[mt][hr] = fb;
                    cnU[mt][hr] = cb;
                }
            }
        }

        bar_named(barid, 64);
    }

    // ---- final reduction: quad lanes -> smem across wn warps -> softplus ----
    #pragma unroll
    for (int mt = 0; mt < 2; mt++) {
        #pragma unroll
        for (int hr = 0; hr < 2; hr++) {
            float fb = fpU[mt][hr], cb = cnU[mt][hr];
            #pragma unroll
            for (int o = 1; o <= 2; o <<= 1) {
                fb = fmaxf(fb, __shfl_xor_sync(0xFFFFFFFFu, fb, o));
                cb = fminf(cb, __shfl_xor_sync(0xFFFFFFFFu, cb, o));
            }
            if (qt == 0) {
                int r = m_base + mt * 16 + hr * 8 + q;
                aggF[wn * 64 + r] = fb;
                aggC[wn * 64 + r] = cb;
            }
        }
    }
    __syncthreads();

    if (tid < 64) {
        float fb = NEGINF, cb = POSINF;
        #pragma unroll
        for (int wnn = 0; wnn < 8; wnn++) {
            fb = fmaxf(fb, aggF[wnn * 64 + tid]);
            cb = fminf(cb, aggC[wnn * 64 + tid]);
        }
        float ssqm = g_ssq[rowbase + tid];
        float fp = (fb < -1e37f) ? 0.f : sqrtf(fmaxf(ssqm + fb, 0.f) + DEPS);
        float cn = sqrtf(fmaxf(ssqm + cb, 0.f) + DEPS);
        float z = fp - cn;
        diff_out[rowbase + tid] = fmaxf(z, 0.f) + log1pf(expf(-fabsf(z)));
    }
}

// ---------------------------------------------------------------------------
// Launch
// Inputs: x[N,128] f32, wv[N,300] f32, label[N] i32, alpha[N,1] f32,
//         W[128,300] f32, b[128] f32
// Output: diff[N] then sem[N,128] (float32, concatenated)
// ---------------------------------------------------------------------------
extern "C" void kernel_launch(void* const* d_in, const int* in_sizes, int n_in,
                              void* d_out, int out_size)
{
    const float* x     = (const float*)d_in[0];
    const float* wv    = (const float*)d_in[1];
    const int*   label = (const int*)  d_in[2];
    const float* alpha = (const float*)d_in[3];
    const float* W     = (const float*)d_in[4];
    const float* b     = (const float*)d_in[5];

    float* out  = (float*)d_out;
    float* diff = out;            // [N]
    float* sem  = out + NROWS;    // [N, 128]

    static bool attr_set = false;
    if (!attr_set) {
        cudaFuncSetAttribute(dist_persist,
                             cudaFuncAttributeMaxDynamicSharedMemorySize, DIST_DSMEM);
        cudaFuncSetAttribute(fc_mix_fused,
                             cudaFuncAttributeMaxDynamicSharedMemorySize, FC_SMEM);
        attr_set = true;
    }

    fc_mix_fused<<<NROWS / FC_ROWS, 256, FC_SMEM>>>(wv, W, b, alpha, x, sem);
    dist_persist<<<NROWS / 64, 512, DIST_DSMEM>>>(label, diff);
}